// round 16
// baseline (speedup 1.0000x reference)
#include <cuda_runtime.h>

#define DFEAT 128
#define SA 136
#define SB 136
#define MAXN 100000
#define MAXE 655360

// ---- persistent device scratch (allocation-free rule: __device__ globals) ----
__device__ int      g_cnt[MAXN];
__device__ int      g_col[MAXN * 32];
__device__ int      g_ovf[2 * MAXE];
__device__ int      g_ovf_n;
__device__ unsigned g_work[2];
__device__ float    g_sum[DFEAT];
__device__ float    g_sq[DFEAT];
__device__ float    g_scale[DFEAT];
__device__ float    g_shift[DFEAT];
__device__ int      g_idx_is64;

__device__ __forceinline__ unsigned f2tf32(float f) {
    unsigned u;
    asm("cvt.rna.tf32.f32 %0, %1;" : "=r"(u) : "f"(f));
    return u;
}

#define MMA_TF32_S(d, a0, a1, a2, a3, b0, b1) \
    asm volatile("mma.sync.aligned.m16n8k8.row.col.f32.tf32.tf32.f32 " \
        "{%0,%1,%2,%3}, {%4,%5,%6,%7}, {%8,%9}, {%0,%1,%2,%3};" \
        : "+f"((d)[0]), "+f"((d)[1]), "+f"((d)[2]), "+f"((d)[3]) \
        : "r"(a0), "r"(a1), "r"(a2), "r"(a3), "r"(b0), "r"(b1))

// half-CTA barrier: ids 1 and 2, 128 threads each
#define BARH(h) asm volatile("bar.sync %0, %1;" :: "r"((h) + 1), "r"(128) : "memory")

#define ADD_F32X2(d, a) \
    asm("add.rn.f32x2 %0, %0, %1;" : "+l"(d) : "l"(a))

// ============================================================================
// K0: zero counters/stats/work + detect edge dtype (block 0)
// ============================================================================
__global__ void zero_kernel(const long long* __restrict__ ei, int E, int M)
{
    int i = blockIdx.x * blockDim.x + threadIdx.x;
    if (i < M) g_cnt[i] = 0;
    if (blockIdx.x == 0) {
        int t = threadIdx.x;
        if (t < DFEAT) { g_sum[t] = 0.f; g_sq[t] = 0.f; }
        if (t == 0) g_ovf_n = 0;
        if (t < 2) g_work[t] = 0u;
        __shared__ unsigned w[2];
        int n = 2 * E < 64 ? 2 * E : 64;
        if (t < 64) {
            bool ok = true;
            if (t < n) {
                long long v = ei[t];
                ok = (v >= 0) && (v < (long long)M);
            }
            unsigned b = __ballot_sync(0xffffffffu, ok);
            if ((t & 31) == 0) w[t >> 5] = b;
        }
        __syncthreads();
        if (t == 0)
            g_idx_is64 = (w[0] == 0xffffffffu && w[1] == 0xffffffffu) ? 1 : 0;
    }
}

// ============================================================================
// K1: build padded CSR (32 slots/node; overflow -> list)
// ============================================================================
__global__ void fill_kernel(const void* __restrict__ ei_raw, int E, int M)
{
    int e = blockIdx.x * blockDim.x + threadIdx.x;
    if (e >= E) return;
    unsigned long long s, d;
    if (g_idx_is64) {
        const long long* ei = (const long long*)ei_raw;
        s = (unsigned long long)ei[e];
        d = (unsigned long long)ei[E + e];
    } else {
        const int* ei = (const int*)ei_raw;
        s = (unsigned long long)(unsigned)ei[e];
        d = (unsigned long long)(unsigned)ei[E + e];
    }
    if (s >= (unsigned long long)M || d >= (unsigned long long)M) return;
    int pos = atomicAdd(&g_cnt[(int)d], 1);
    if (pos < 32) {
        g_col[(int)d * 32 + pos] = (int)s;
    } else {
        int o = atomicAdd(&g_ovf_n, 1);
        if (o < MAXE) { g_ovf[2 * o] = (int)s; g_ovf[2 * o + 1] = (int)d; }
    }
}

// ============================================================================
// K2: gather-sum (L2-BW bound): out[n] = sum_nbr x[src] + (1+eps) x[n]
// packed f32x2 accumulation halves the FADD issue load.
// ============================================================================
__global__ void gather_kernel(const float4* __restrict__ x,
                              float4* __restrict__ out,
                              const float* __restrict__ eps,
                              int M)
{
    int node = blockIdx.x * 8 + (threadIdx.x >> 5);
    if (node >= M) return;
    int lane = threadIdx.x & 31;

    int cnt = g_cnt[node];
    if (cnt > 32) cnt = 32;
    int src = (lane < cnt) ? g_col[node * 32 + lane] : 0;

    float c = 1.0f + *eps;
    float4 a = x[(long)node * 32 + lane];
    a.x *= c; a.y *= c; a.z *= c; a.w *= c;
    unsigned long long p0, p1;
    asm("mov.b64 %0, {%1, %2};" : "=l"(p0)
        : "r"(__float_as_uint(a.x)), "r"(__float_as_uint(a.y)));
    asm("mov.b64 %0, {%1, %2};" : "=l"(p1)
        : "r"(__float_as_uint(a.z)), "r"(__float_as_uint(a.w)));

    #pragma unroll 4
    for (int j = 0; j < cnt; j++) {
        int s = __shfl_sync(0xffffffffu, src, j);
        ulonglong2 u = *reinterpret_cast<const ulonglong2*>(
            x + (long)s * 32 + lane);
        ADD_F32X2(p0, u.x);
        ADD_F32X2(p1, u.y);
    }
    ulonglong2 o; o.x = p0; o.y = p1;
    *reinterpret_cast<ulonglong2*>(out + (long)node * 32 + lane) = o;
}

// ============================================================================
// K3: overflow edges (deg>32) — atomic fallback; nearly always 0 edges.
// ============================================================================
__global__ void ovf_kernel(const float4* __restrict__ x,
                           float4* __restrict__ out)
{
    int n = g_ovf_n;
    if (n > MAXE) n = MAXE;
    int lane = threadIdx.x & 31;
    for (int i = blockIdx.x * 8 + (threadIdx.x >> 5); i < n; i += gridDim.x * 8) {
        int s = g_ovf[2 * i], d = g_ovf[2 * i + 1];
        atomicAdd(&out[(long)d * 32 + lane], x[(long)s * 32 + lane]);
    }
}

// ============================================================================
// K4/K6: PERSISTENT in-place GEMM (mma.sync tf32), split-half CTAs with
// ATOMIC WORK-STEALING (near-perfect chunk balance, no static tail).
//   C[M,128] = f(C) @ W + bias
//   - 8 warps = two independent 128-thread halves; own A buffer, own named
//     barrier, own dynamically-stolen chunk stream.
//   - B (W) loaded once per CTA (k-rows permuted).
//   - next chunk's A prefetched into regs during current chunk's MMAs.
//   - PHASE 1: BN stats in regs, flushed once per warp.
//   - PHASE 2: ReLU(BN(.)) applied at A store-to-smem.
// ============================================================================
template <int PHASE>
__global__ __launch_bounds__(256, 2)
void gemm_tc_kernel(float* __restrict__ C,
                    const float* __restrict__ W,
                    const float* __restrict__ bias,
                    int M, int nchunks)
{
    extern __shared__ unsigned smem_u[];
    unsigned* Bs = smem_u + 64 * SA;
    __shared__ float s_scale[DFEAT];
    __shared__ float s_shift[DFEAT];
    __shared__ int   s_chunk[2];

    const int t    = threadIdx.x;
    const int lane = t & 31;
    const int warp = t >> 5;
    const int h    = warp >> 2;       // half 0/1
    const int w4   = warp & 3;        // warp within half = n-quarter
    unsigned* Ah   = smem_u + h * (32 * SA);

    // ---- steal first chunk ----
    if ((t & 127) == 0) s_chunk[h] = (int)atomicAdd(&g_work[PHASE - 1], 1u);
    __syncthreads();
    int chunk = s_chunk[h];

    // ---- prefetch first chunk's A into registers ----
    float4 areg[8];
    if (chunk < nchunks) {
#pragma unroll
        for (int i = 0; i < 8; i++) {
            int m = chunk * 32 + i * 4 + w4;
            areg[i] = (m < M)
                ? *reinterpret_cast<const float4*>(C + (long)m * DFEAT + lane * 4)
                : make_float4(0.f, 0.f, 0.f, 0.f);
        }
    }

    if (PHASE == 2) {
        if (t < DFEAT) { s_scale[t] = g_scale[t]; s_shift[t] = g_shift[t]; }
    }

    // ---- load B tile ONCE (cooperative, all 8 warps), k-rows permuted ----
#pragma unroll
    for (int i = 0; i < 16; i++) {
        int k  = i * 8 + warp;
        int nk = (k & ~7) | ((k & 1) << 2) | ((k & 7) >> 1);
        float4 v = *reinterpret_cast<const float4*>(W + (long)k * DFEAT + lane * 4);
        uint4 u = make_uint4(f2tf32(v.x), f2tf32(v.y), f2tf32(v.z), f2tf32(v.w));
        *reinterpret_cast<uint4*>(Bs + nk * SB + lane * 4) = u;
    }

    const int q  = lane & 3;
    const int rg = lane >> 2;

    float bv[4][2];
#pragma unroll
    for (int nt = 0; nt < 4; nt++) {
        int col = w4 * 32 + nt * 8 + 2 * q;
        bv[nt][0] = bias[col];
        bv[nt][1] = bias[col + 1];
    }

    float csum[4][2] = {{0.f,0.f},{0.f,0.f},{0.f,0.f},{0.f,0.f}};
    float csq [4][2] = {{0.f,0.f},{0.f,0.f},{0.f,0.f},{0.f,0.f}};

    const unsigned* Abase = Ah + rg * SA + 2 * q;
    const unsigned* Bbase = Bs + q * SB + w4 * 32 + rg;
    unsigned* Asts = Ah + w4 * SA + lane * 4;

    __syncthreads();   // B (and s_scale) visible to all

    while (chunk < nchunks) {
        // ---- store current A chunk to this half's smem buffer ----
#pragma unroll
        for (int i = 0; i < 8; i++) {
            float4 v = areg[i];
            if (PHASE == 2) {
                int kb = lane * 4;
                v.x = fmaxf(fmaf(v.x, s_scale[kb + 0], s_shift[kb + 0]), 0.f);
                v.y = fmaxf(fmaf(v.y, s_scale[kb + 1], s_shift[kb + 1]), 0.f);
                v.z = fmaxf(fmaf(v.z, s_scale[kb + 2], s_shift[kb + 2]), 0.f);
                v.w = fmaxf(fmaf(v.w, s_scale[kb + 3], s_shift[kb + 3]), 0.f);
            }
            uint4 u = make_uint4(f2tf32(v.x), f2tf32(v.y), f2tf32(v.z), f2tf32(v.w));
            *reinterpret_cast<uint4*>(Asts + i * 4 * SA) = u;
        }
        // ---- steal next chunk (atomic hidden behind barrier + prefetch) ----
        if ((t & 127) == 0) s_chunk[h] = (int)atomicAdd(&g_work[PHASE - 1], 1u);
        BARH(h);
        int next = s_chunk[h];

        // ---- prefetch next chunk's A (overlaps MMAs below) ----
        if (next < nchunks) {
#pragma unroll
            for (int i = 0; i < 8; i++) {
                int m = next * 32 + i * 4 + w4;
                areg[i] = (m < M)
                    ? *reinterpret_cast<const float4*>(C + (long)m * DFEAT + lane * 4)
                    : make_float4(0.f, 0.f, 0.f, 0.f);
            }
        }

        // ---- MMAs over K=128 (warp tile: 32 rows x 32 cols) ----
        float acc[2][4][4];
#pragma unroll
        for (int mt = 0; mt < 2; mt++)
#pragma unroll
            for (int nt = 0; nt < 4; nt++)
#pragma unroll
                for (int j = 0; j < 4; j++) acc[mt][nt][j] = 0.f;

#pragma unroll
        for (int k0 = 0; k0 < DFEAT; k0 += 8) {
            uint2 alo[2], ahi[2];
#pragma unroll
            for (int mt = 0; mt < 2; mt++) {
                alo[mt] = *reinterpret_cast<const uint2*>(Abase + mt * 16 * SA + k0);
                ahi[mt] = *reinterpret_cast<const uint2*>(Abase + (mt * 16 + 8) * SA + k0);
            }
            unsigned b0[4], b1[4];
#pragma unroll
            for (int nt = 0; nt < 4; nt++) {
                b0[nt] = Bbase[k0 * SB + nt * 8];
                b1[nt] = Bbase[(k0 + 4) * SB + nt * 8];
            }
#pragma unroll
            for (int mt = 0; mt < 2; mt++)
#pragma unroll
                for (int nt = 0; nt < 4; nt++)
                    MMA_TF32_S(acc[mt][nt],
                               alo[mt].x, ahi[mt].x, alo[mt].y, ahi[mt].y,
                               b0[nt], b1[nt]);
        }
        BARH(h);   // half's warps done reading Ah -> next STS is safe

        // ---- epilogue: bias add, in-place store, BN stats (PHASE 1) ----
        int mb = chunk * 32;
#pragma unroll
        for (int mt = 0; mt < 2; mt++) {
            int r0 = mb + mt * 16 + rg;
            int r1 = r0 + 8;
#pragma unroll
            for (int nt = 0; nt < 4; nt++) {
                int col = w4 * 32 + nt * 8 + 2 * q;
                float v0 = acc[mt][nt][0] + bv[nt][0];
                float v1 = acc[mt][nt][1] + bv[nt][1];
                float v2 = acc[mt][nt][2] + bv[nt][0];
                float v3 = acc[mt][nt][3] + bv[nt][1];
                if (r0 < M) {
                    *reinterpret_cast<float2*>(C + (long)r0 * DFEAT + col) =
                        make_float2(v0, v1);
                    if (PHASE == 1) {
                        csum[nt][0] += v0; csq[nt][0] += v0 * v0;
                        csum[nt][1] += v1; csq[nt][1] += v1 * v1;
                    }
                }
                if (r1 < M) {
                    *reinterpret_cast<float2*>(C + (long)r1 * DFEAT + col) =
                        make_float2(v2, v3);
                    if (PHASE == 1) {
                        csum[nt][0] += v2; csq[nt][0] += v2 * v2;
                        csum[nt][1] += v3; csq[nt][1] += v3 * v3;
                    }
                }
            }
        }
        chunk = next;
    }

    if (PHASE == 1) {
#pragma unroll
        for (int nt = 0; nt < 4; nt++)
#pragma unroll
            for (int j = 0; j < 2; j++) {
#pragma unroll
                for (int ofs = 4; ofs < 32; ofs <<= 1) {
                    csum[nt][j] += __shfl_xor_sync(0xffffffffu, csum[nt][j], ofs);
                    csq[nt][j]  += __shfl_xor_sync(0xffffffffu, csq[nt][j],  ofs);
                }
            }
        if (rg == 0) {
#pragma unroll
            for (int nt = 0; nt < 4; nt++) {
                int col = w4 * 32 + nt * 8 + 2 * q;
                atomicAdd(&g_sum[col],     csum[nt][0]);
                atomicAdd(&g_sum[col + 1], csum[nt][1]);
                atomicAdd(&g_sq[col],      csq[nt][0]);
                atomicAdd(&g_sq[col + 1],  csq[nt][1]);
            }
        }
    }
}

// ============================================================================
// K5: fold BN stats into affine scale/shift
// ============================================================================
__global__ void finalize_kernel(const float* __restrict__ gamma,
                                const float* __restrict__ beta,
                                float invM)
{
    int t = threadIdx.x;
    float mu   = g_sum[t] * invM;
    float var  = g_sq[t] * invM - mu * mu;
    float rstd = rsqrtf(var + 1e-5f);
    float sc   = rstd * gamma[t];
    g_scale[t] = sc;
    g_shift[t] = beta[t] - mu * sc;
}

// ============================================================================
// launch: resolve inputs by size signature (robust to metadata ordering)
// ============================================================================
extern "C" void kernel_launch(void* const* d_in, const int* in_sizes, int n_in,
                              void* d_out, int out_size)
{
    int ix = -1, ie = -1, iW1 = -1, iW2 = -1, ieps = -1;
    int v128[8]; int n128 = 0;
    long best_x = -1, best_e = -1;
    for (int i = 0; i < n_in; i++) {
        long sz = in_sizes[i];
        if (sz > best_x) {
            best_e = best_x; ie = ix;
            best_x = sz; ix = i;
        } else if (sz > best_e) { best_e = sz; ie = i; }
    }
    for (int i = 0; i < n_in; i++) {
        if (i == ix || i == ie) continue;
        long sz = in_sizes[i];
        if (sz == DFEAT * DFEAT) { if (iW1 < 0) iW1 = i; else iW2 = i; }
        else if (sz == DFEAT)    { if (n128 < 8) v128[n128++] = i; }
        else                     { ieps = i; }
    }
    int ib1, igamma, ibeta, ib2;
    if (ix == 0) { ib1 = v128[0]; igamma = v128[1]; ibeta = v128[2]; ib2 = v128[3]; }
    else         { ib1 = v128[0]; ib2 = v128[1];    ibeta = v128[2]; igamma = v128[3]; }

    const float* x     = (const float*)d_in[ix];
    const void*  ei    = d_in[ie];
    const float* W1    = (const float*)d_in[iW1];
    const float* b1    = (const float*)d_in[ib1];
    const float* gamma = (const float*)d_in[igamma];
    const float* beta  = (const float*)d_in[ibeta];
    const float* W2    = (const float*)d_in[iW2];
    const float* b2    = (const float*)d_in[ib2];
    const float* eps   = (const float*)d_in[ieps];
    float*       out   = (float*)d_out;

    int M = in_sizes[ix] / DFEAT;
    int E = in_sizes[ie] / 2;
    if (M > MAXN) M = MAXN;   // static bucket capacity guard

    static int nsm = 0;
    const int dyn_smem = (64 * SA + 128 * SB) * 4;   // 104,448 B -> 2 CTA/SM
    if (!nsm) {
        cudaFuncSetAttribute(gemm_tc_kernel<1>,
                             cudaFuncAttributeMaxDynamicSharedMemorySize, dyn_smem);
        cudaFuncSetAttribute(gemm_tc_kernel<2>,
                             cudaFuncAttributeMaxDynamicSharedMemorySize, dyn_smem);
        cudaDeviceGetAttribute(&nsm, cudaDevAttrMultiProcessorCount, 0);
        if (nsm <= 0) nsm = 148;
    }

    // K0: zero counters/stats/work + detect dtype
    zero_kernel<<<(M + 255) / 256, 256>>>((const long long*)ei, E, M);

    // K1: bucket edges by dst (padded CSR)
    fill_kernel<<<(E + 255) / 256, 256>>>(ei, E, M);

    // K2: out[n] = sum_nbr x[src] + (1+eps) x[n]
    gather_kernel<<<(M + 7) / 8, 256>>>((const float4*)x, (float4*)out, eps, M);

    // K3: rare deg>32 overflow edges via atomics
    ovf_kernel<<<8, 256>>>((const float4*)x, (float4*)out);

    int nchunks = (M + 31) / 32;
    int pgrid   = 2 * nsm;
    int maxg    = (nchunks + 1) / 2;
    if (pgrid > maxg) pgrid = maxg;

    // K4: out = out @ W1 + b1 (in place, work-stealing), BN stats
    gemm_tc_kernel<1><<<pgrid, 256, dyn_smem>>>(out, W1, b1, M, nchunks);

    // K5: fold mean/var/gamma/beta into scale/shift
    finalize_kernel<<<1, DFEAT>>>(gamma, beta, 1.0f / (float)M);

    // K6: out = ReLU(BN(out)) @ W2 + b2 (in place, work-stealing)
    gemm_tc_kernel<2><<<pgrid, 256, dyn_smem>>>(out, W2, b2, M, nchunks);
}

// round 17
// speedup vs baseline: 1.0528x; 1.0528x over previous
#include <cuda_runtime.h>

#define DFEAT 128
#define SA 136
#define SB 136
#define MAXN 100000
#define MAXE 655360

// ---- persistent device scratch (allocation-free rule: __device__ globals) ----
__device__ int   g_cnt[MAXN];
__device__ int   g_col[MAXN * 32];
__device__ int   g_ovf[2 * MAXE];
__device__ int   g_ovf_n;
__device__ float g_sum[DFEAT];
__device__ float g_sq[DFEAT];
__device__ float g_scale[DFEAT];
__device__ float g_shift[DFEAT];
__device__ int   g_idx_is64;

__device__ __forceinline__ unsigned f2tf32(float f) {
    unsigned u;
    asm("cvt.rna.tf32.f32 %0, %1;" : "=r"(u) : "f"(f));
    return u;
}

#define MMA_TF32_S(d, a0, a1, a2, a3, b0, b1) \
    asm volatile("mma.sync.aligned.m16n8k8.row.col.f32.tf32.tf32.f32 " \
        "{%0,%1,%2,%3}, {%4,%5,%6,%7}, {%8,%9}, {%0,%1,%2,%3};" \
        : "+f"((d)[0]), "+f"((d)[1]), "+f"((d)[2]), "+f"((d)[3]) \
        : "r"(a0), "r"(a1), "r"(a2), "r"(a3), "r"(b0), "r"(b1))

// half-CTA barrier: ids 1 and 2, 128 threads each (id 0 = __syncthreads)
#define BARH(h) asm volatile("bar.sync %0, %1;" :: "r"((h) + 1), "r"(128) : "memory")

// ============================================================================
// K0: zero counters/stats + detect edge dtype (block 0)
// ============================================================================
__global__ void zero_kernel(const long long* __restrict__ ei, int E, int M)
{
    int i = blockIdx.x * blockDim.x + threadIdx.x;
    if (i < M) g_cnt[i] = 0;
    if (blockIdx.x == 0) {
        int t = threadIdx.x;
        if (t < DFEAT) { g_sum[t] = 0.f; g_sq[t] = 0.f; }
        if (t == 0) g_ovf_n = 0;
        __shared__ unsigned w[2];
        int n = 2 * E < 64 ? 2 * E : 64;
        if (t < 64) {
            bool ok = true;
            if (t < n) {
                long long v = ei[t];
                ok = (v >= 0) && (v < (long long)M);
            }
            unsigned b = __ballot_sync(0xffffffffu, ok);
            if ((t & 31) == 0) w[t >> 5] = b;
        }
        __syncthreads();
        if (t == 0)
            g_idx_is64 = (w[0] == 0xffffffffu && w[1] == 0xffffffffu) ? 1 : 0;
    }
}

// ============================================================================
// K1: build padded CSR — bucket src indices by dst (32 slots/node; overflow
// edges appended to a list handled by the atomic fallback kernel).
// ============================================================================
__global__ void fill_kernel(const void* __restrict__ ei_raw, int E, int M)
{
    int e = blockIdx.x * blockDim.x + threadIdx.x;
    if (e >= E) return;
    unsigned long long s, d;
    if (g_idx_is64) {
        const long long* ei = (const long long*)ei_raw;
        s = (unsigned long long)ei[e];
        d = (unsigned long long)ei[E + e];
    } else {
        const int* ei = (const int*)ei_raw;
        s = (unsigned long long)(unsigned)ei[e];
        d = (unsigned long long)(unsigned)ei[E + e];
    }
    if (s >= (unsigned long long)M || d >= (unsigned long long)M) return;
    int pos = atomicAdd(&g_cnt[(int)d], 1);
    if (pos < 32) {
        g_col[(int)d * 32 + pos] = (int)s;
    } else {
        int o = atomicAdd(&g_ovf_n, 1);
        if (o < MAXE) { g_ovf[2 * o] = (int)s; g_ovf[2 * o + 1] = (int)d; }
    }
}

// ============================================================================
// K2: gather-sum (at the LTS ceiling — ~433MB L2 traffic = ~38 us floor):
//   out[node] = sum_{src in nbr(node)} x[src] + (1+eps) * x[node]
// ============================================================================
__global__ void gather_kernel(const float4* __restrict__ x,
                              float4* __restrict__ out,
                              const float* __restrict__ eps,
                              int M)
{
    int node = blockIdx.x * 8 + (threadIdx.x >> 5);
    if (node >= M) return;
    int lane = threadIdx.x & 31;

    int cnt = g_cnt[node];
    if (cnt > 32) cnt = 32;
    int src = (lane < cnt) ? g_col[node * 32 + lane] : 0;

    float c = 1.0f + *eps;
    float4 acc = x[(long)node * 32 + lane];
    acc.x *= c; acc.y *= c; acc.z *= c; acc.w *= c;

    #pragma unroll 4
    for (int j = 0; j < cnt; j++) {
        int s = __shfl_sync(0xffffffffu, src, j);
        float4 v = x[(long)s * 32 + lane];
        acc.x += v.x; acc.y += v.y; acc.z += v.z; acc.w += v.w;
    }
    out[(long)node * 32 + lane] = acc;
}

// ============================================================================
// K3: overflow edges (deg>32) — atomic fallback; nearly always 0 edges.
// ============================================================================
__global__ void ovf_kernel(const float4* __restrict__ x,
                           float4* __restrict__ out)
{
    int n = g_ovf_n;
    if (n > MAXE) n = MAXE;
    int lane = threadIdx.x & 31;
    for (int i = blockIdx.x * 8 + (threadIdx.x >> 5); i < n; i += gridDim.x * 8) {
        int s = g_ovf[2 * i], d = g_ovf[2 * i + 1];
        atomicAdd(&out[(long)d * 32 + lane], x[(long)s * 32 + lane]);
    }
}

// ============================================================================
// K4/K6: PERSISTENT in-place GEMM (mma.sync tf32), SPLIT-HALF CTAs,
// STATIC chunk striding (work-stealing measured -4.6us: steal atomic sits on
// the prefetch critical path).
//   C[M,128] = f(C) @ W + bias
//   - 8 warps = two independent 128-thread halves; each half owns a 32-row
//     A buffer + its own chunk stream + its own named barrier.
//   - B (W) loaded once per CTA (k-rows permuted).
//   - next chunk's A prefetched into regs during current chunk's MMAs.
//   - PHASE 1: BN stats in regs, flushed once per warp.
//   - PHASE 2: ReLU(BN(.)) applied at A store-to-smem.
// ============================================================================
template <int PHASE>
__global__ __launch_bounds__(256, 2)
void gemm_tc_kernel(float* __restrict__ C,
                    const float* __restrict__ W,
                    const float* __restrict__ bias,
                    int M, int nchunks)
{
    extern __shared__ unsigned smem_u[];
    unsigned* Bs = smem_u + 64 * SA;
    __shared__ float s_scale[DFEAT];
    __shared__ float s_shift[DFEAT];

    const int t    = threadIdx.x;
    const int lane = t & 31;
    const int warp = t >> 5;
    const int h    = warp >> 2;       // half 0/1
    const int w4   = warp & 3;        // warp within half = n-quarter
    unsigned* Ah   = smem_u + h * (32 * SA);

    // ---- prefetch first chunk's A into registers ----
    int chunk = blockIdx.x * 2 + h;
    float4 areg[8];
    if (chunk < nchunks) {
#pragma unroll
        for (int i = 0; i < 8; i++) {
            int m = chunk * 32 + i * 4 + w4;
            areg[i] = (m < M)
                ? *reinterpret_cast<const float4*>(C + (long)m * DFEAT + lane * 4)
                : make_float4(0.f, 0.f, 0.f, 0.f);
        }
    }

    if (PHASE == 2) {
        if (t < DFEAT) { s_scale[t] = g_scale[t]; s_shift[t] = g_shift[t]; }
    }

    // ---- load B tile ONCE (cooperative, all 8 warps), k-rows permuted ----
#pragma unroll
    for (int i = 0; i < 16; i++) {
        int k  = i * 8 + warp;
        int nk = (k & ~7) | ((k & 1) << 2) | ((k & 7) >> 1);
        float4 v = *reinterpret_cast<const float4*>(W + (long)k * DFEAT + lane * 4);
        uint4 u = make_uint4(f2tf32(v.x), f2tf32(v.y), f2tf32(v.z), f2tf32(v.w));
        *reinterpret_cast<uint4*>(Bs + nk * SB + lane * 4) = u;
    }

    const int q  = lane & 3;
    const int rg = lane >> 2;

    float bv[4][2];
#pragma unroll
    for (int nt = 0; nt < 4; nt++) {
        int col = w4 * 32 + nt * 8 + 2 * q;
        bv[nt][0] = bias[col];
        bv[nt][1] = bias[col + 1];
    }

    float csum[4][2] = {{0.f,0.f},{0.f,0.f},{0.f,0.f},{0.f,0.f}};
    float csq [4][2] = {{0.f,0.f},{0.f,0.f},{0.f,0.f},{0.f,0.f}};

    const unsigned* Abase = Ah + rg * SA + 2 * q;
    const unsigned* Bbase = Bs + q * SB + w4 * 32 + rg;
    unsigned* Asts = Ah + w4 * SA + lane * 4;

    __syncthreads();   // B (and s_scale) visible to all

    while (chunk < nchunks) {
        // ---- store current A chunk to this half's smem buffer ----
#pragma unroll
        for (int i = 0; i < 8; i++) {
            float4 v = areg[i];
            if (PHASE == 2) {
                int kb = lane * 4;
                v.x = fmaxf(fmaf(v.x, s_scale[kb + 0], s_shift[kb + 0]), 0.f);
                v.y = fmaxf(fmaf(v.y, s_scale[kb + 1], s_shift[kb + 1]), 0.f);
                v.z = fmaxf(fmaf(v.z, s_scale[kb + 2], s_shift[kb + 2]), 0.f);
                v.w = fmaxf(fmaf(v.w, s_scale[kb + 3], s_shift[kb + 3]), 0.f);
            }
            uint4 u = make_uint4(f2tf32(v.x), f2tf32(v.y), f2tf32(v.z), f2tf32(v.w));
            *reinterpret_cast<uint4*>(Asts + i * 4 * SA) = u;
        }
        BARH(h);

        // ---- prefetch next chunk's A (overlaps MMAs below) ----
        int next = chunk + gridDim.x * 2;
        if (next < nchunks) {
#pragma unroll
            for (int i = 0; i < 8; i++) {
                int m = next * 32 + i * 4 + w4;
                areg[i] = (m < M)
                    ? *reinterpret_cast<const float4*>(C + (long)m * DFEAT + lane * 4)
                    : make_float4(0.f, 0.f, 0.f, 0.f);
            }
        }

        // ---- MMAs over K=128 (warp tile: 32 rows x 32 cols) ----
        float acc[2][4][4];
#pragma unroll
        for (int mt = 0; mt < 2; mt++)
#pragma unroll
            for (int nt = 0; nt < 4; nt++)
#pragma unroll
                for (int j = 0; j < 4; j++) acc[mt][nt][j] = 0.f;

#pragma unroll
        for (int k0 = 0; k0 < DFEAT; k0 += 8) {
            uint2 alo[2], ahi[2];
#pragma unroll
            for (int mt = 0; mt < 2; mt++) {
                alo[mt] = *reinterpret_cast<const uint2*>(Abase + mt * 16 * SA + k0);
                ahi[mt] = *reinterpret_cast<const uint2*>(Abase + (mt * 16 + 8) * SA + k0);
            }
            unsigned b0[4], b1[4];
#pragma unroll
            for (int nt = 0; nt < 4; nt++) {
                b0[nt] = Bbase[k0 * SB + nt * 8];
                b1[nt] = Bbase[(k0 + 4) * SB + nt * 8];
            }
#pragma unroll
            for (int mt = 0; mt < 2; mt++)
#pragma unroll
                for (int nt = 0; nt < 4; nt++)
                    MMA_TF32_S(acc[mt][nt],
                               alo[mt].x, ahi[mt].x, alo[mt].y, ahi[mt].y,
                               b0[nt], b1[nt]);
        }
        BARH(h);   // half's warps done reading Ah -> next STS is safe

        // ---- epilogue: bias add, in-place store, BN stats (PHASE 1) ----
        int mb = chunk * 32;
#pragma unroll
        for (int mt = 0; mt < 2; mt++) {
            int r0 = mb + mt * 16 + rg;
            int r1 = r0 + 8;
#pragma unroll
            for (int nt = 0; nt < 4; nt++) {
                int col = w4 * 32 + nt * 8 + 2 * q;
                float v0 = acc[mt][nt][0] + bv[nt][0];
                float v1 = acc[mt][nt][1] + bv[nt][1];
                float v2 = acc[mt][nt][2] + bv[nt][0];
                float v3 = acc[mt][nt][3] + bv[nt][1];
                if (r0 < M) {
                    *reinterpret_cast<float2*>(C + (long)r0 * DFEAT + col) =
                        make_float2(v0, v1);
                    if (PHASE == 1) {
                        csum[nt][0] += v0; csq[nt][0] += v0 * v0;
                        csum[nt][1] += v1; csq[nt][1] += v1 * v1;
                    }
                }
                if (r1 < M) {
                    *reinterpret_cast<float2*>(C + (long)r1 * DFEAT + col) =
                        make_float2(v2, v3);
                    if (PHASE == 1) {
                        csum[nt][0] += v2; csq[nt][0] += v2 * v2;
                        csum[nt][1] += v3; csq[nt][1] += v3 * v3;
                    }
                }
            }
        }
        chunk = next;
    }

    if (PHASE == 1) {
#pragma unroll
        for (int nt = 0; nt < 4; nt++)
#pragma unroll
            for (int j = 0; j < 2; j++) {
#pragma unroll
                for (int ofs = 4; ofs < 32; ofs <<= 1) {
                    csum[nt][j] += __shfl_xor_sync(0xffffffffu, csum[nt][j], ofs);
                    csq[nt][j]  += __shfl_xor_sync(0xffffffffu, csq[nt][j],  ofs);
                }
            }
        if (rg == 0) {
#pragma unroll
            for (int nt = 0; nt < 4; nt++) {
                int col = w4 * 32 + nt * 8 + 2 * q;
                atomicAdd(&g_sum[col],     csum[nt][0]);
                atomicAdd(&g_sum[col + 1], csum[nt][1]);
                atomicAdd(&g_sq[col],      csq[nt][0]);
                atomicAdd(&g_sq[col + 1],  csq[nt][1]);
            }
        }
    }
}

// ============================================================================
// K5: fold BN stats into affine scale/shift
// ============================================================================
__global__ void finalize_kernel(const float* __restrict__ gamma,
                                const float* __restrict__ beta,
                                float invM)
{
    int t = threadIdx.x;
    float mu   = g_sum[t] * invM;
    float var  = g_sq[t] * invM - mu * mu;
    float rstd = rsqrtf(var + 1e-5f);
    float sc   = rstd * gamma[t];
    g_scale[t] = sc;
    g_shift[t] = beta[t] - mu * sc;
}

// ============================================================================
// launch: resolve inputs by size signature (robust to metadata ordering)
// ============================================================================
extern "C" void kernel_launch(void* const* d_in, const int* in_sizes, int n_in,
                              void* d_out, int out_size)
{
    int ix = -1, ie = -1, iW1 = -1, iW2 = -1, ieps = -1;
    int v128[8]; int n128 = 0;
    long best_x = -1, best_e = -1;
    for (int i = 0; i < n_in; i++) {
        long sz = in_sizes[i];
        if (sz > best_x) {
            best_e = best_x; ie = ix;
            best_x = sz; ix = i;
        } else if (sz > best_e) { best_e = sz; ie = i; }
    }
    for (int i = 0; i < n_in; i++) {
        if (i == ix || i == ie) continue;
        long sz = in_sizes[i];
        if (sz == DFEAT * DFEAT) { if (iW1 < 0) iW1 = i; else iW2 = i; }
        else if (sz == DFEAT)    { if (n128 < 8) v128[n128++] = i; }
        else                     { ieps = i; }
    }
    int ib1, igamma, ibeta, ib2;
    if (ix == 0) { ib1 = v128[0]; igamma = v128[1]; ibeta = v128[2]; ib2 = v128[3]; }
    else         { ib1 = v128[0]; ib2 = v128[1];    ibeta = v128[2]; igamma = v128[3]; }

    const float* x     = (const float*)d_in[ix];
    const void*  ei    = d_in[ie];
    const float* W1    = (const float*)d_in[iW1];
    const float* b1    = (const float*)d_in[ib1];
    const float* gamma = (const float*)d_in[igamma];
    const float* beta  = (const float*)d_in[ibeta];
    const float* W2    = (const float*)d_in[iW2];
    const float* b2    = (const float*)d_in[ib2];
    const float* eps   = (const float*)d_in[ieps];
    float*       out   = (float*)d_out;

    int M = in_sizes[ix] / DFEAT;
    int E = in_sizes[ie] / 2;
    if (M > MAXN) M = MAXN;   // static bucket capacity guard

    static int nsm = 0;
    const int dyn_smem = (64 * SA + 128 * SB) * 4;   // 104,448 B -> 2 CTA/SM
    if (!nsm) {
        cudaFuncSetAttribute(gemm_tc_kernel<1>,
                             cudaFuncAttributeMaxDynamicSharedMemorySize, dyn_smem);
        cudaFuncSetAttribute(gemm_tc_kernel<2>,
                             cudaFuncAttributeMaxDynamicSharedMemorySize, dyn_smem);
        cudaDeviceGetAttribute(&nsm, cudaDevAttrMultiProcessorCount, 0);
        if (nsm <= 0) nsm = 148;
    }

    // K0: zero counters + BN stats + detect dtype (merged)
    zero_kernel<<<(M + 255) / 256, 256>>>((const long long*)ei, E, M);

    // K1: bucket edges by dst (padded CSR)
    fill_kernel<<<(E + 255) / 256, 256>>>(ei, E, M);

    // K2: out[n] = sum_nbr x[src] + (1+eps) x[n]
    gather_kernel<<<(M + 7) / 8, 256>>>((const float4*)x, (float4*)out, eps, M);

    // K3: rare deg>32 overflow edges via atomics
    ovf_kernel<<<64, 256>>>((const float4*)x, (float4*)out);

    int nchunks = (M + 31) / 32;
    int pgrid   = 2 * nsm;
    int maxg    = (nchunks + 1) / 2;
    if (pgrid > maxg) pgrid = maxg;

    // K4: out = out @ W1 + b1 (in place, persistent, split-half), BN stats
    gemm_tc_kernel<1><<<pgrid, 256, dyn_smem>>>(out, W1, b1, M, nchunks);

    // K5: fold mean/var/gamma/beta into scale/shift
    finalize_kernel<<<1, DFEAT>>>(gamma, beta, 1.0f / (float)M);

    // K6: out = ReLU(BN(out)) @ W2 + b2 (in place, persistent, split-half)
    gemm_tc_kernel<2><<<pgrid, 256, dyn_smem>>>(out, W2, b2, M, nchunks);
}